// round 1
// baseline (speedup 1.0000x reference)
#include <cuda_runtime.h>
#include <cstdint>

#define S 256            // superpixels per batch
#define B 8
#define HW 262144        // 512*512, pixels per batch
#define C 64
#define NSEG (B * S)     // 2048 global segments
#define CAP 2048         // bucket capacity per segment (max expected ~1140)
#define CNT_STRIDE 32    // 128B padding between counters (L2-partition spread)

// Scratch (allocation-free: __device__ globals)
__device__ int g_cnt[NSEG * CNT_STRIDE];            // 256 KB
__device__ int g_idx[(size_t)NSEG * CAP];           // 16 MB

// ---------------- Kernel 0: zero counters ----------------
__global__ void k_zero() {
    int t = blockIdx.x * blockDim.x + threadIdx.x;
    if (t < NSEG * CNT_STRIDE) g_cnt[t] = 0;
}

// ---------------- Kernel 1: scatter pixel indices into per-segment buckets ----------------
__global__ void k_scatter(const int* __restrict__ sp) {
    int t = blockIdx.x * blockDim.x + threadIdx.x;   // global pixel id, exact grid
    int b   = t >> 18;                                // t / HW
    int pix = t & (HW - 1);
    int seg = sp[t];
    int g   = b * S + seg;
    int pos = atomicAdd(&g_cnt[g * CNT_STRIDE], 1);
    if (pos < CAP) g_idx[(size_t)g * CAP + pos] = pix;
}

// ---------------- Kernel 2: per-segment gather + mean ----------------
// One CTA per global segment. 256 threads = 8 warps.
// Warp handles pixels i, i+8, i+16, ... ; lane l owns channels (2l, 2l+1).
__global__ void __launch_bounds__(256, 4) k_reduce(const float* __restrict__ feat,
                                                   float* __restrict__ out) {
    __shared__ int   sidx[CAP];          // 8 KB
    __shared__ float sred[8 * C];        // 2 KB

    const int g   = blockIdx.x;          // global segment
    const int b   = g >> 8;              // g / S
    const int tid = threadIdx.x;
    const int wid = tid >> 5;
    const int ln  = tid & 31;

    int n = g_cnt[g * CNT_STRIDE];
    if (n > CAP) n = CAP;

    // stage indices in smem (coalesced)
    for (int i = tid; i < n; i += 256) sidx[i] = g_idx[(size_t)g * CAP + i];
    __syncthreads();

    const float* fb = feat + (size_t)b * HW * C;

    float2 a0 = make_float2(0.f, 0.f), a1 = a0, a2 = a0, a3 = a0;
    int i = wid;
    // 4-way unroll: 4 independent 256B gathers in flight per warp (MLP)
    for (; i + 24 < n; i += 32) {
        const float2 v0 = *(const float2*)(fb + (size_t)sidx[i     ] * C + 2 * ln);
        const float2 v1 = *(const float2*)(fb + (size_t)sidx[i +  8] * C + 2 * ln);
        const float2 v2 = *(const float2*)(fb + (size_t)sidx[i + 16] * C + 2 * ln);
        const float2 v3 = *(const float2*)(fb + (size_t)sidx[i + 24] * C + 2 * ln);
        a0.x += v0.x; a0.y += v0.y;
        a1.x += v1.x; a1.y += v1.y;
        a2.x += v2.x; a2.y += v2.y;
        a3.x += v3.x; a3.y += v3.y;
    }
    for (; i < n; i += 8) {
        const float2 v = *(const float2*)(fb + (size_t)sidx[i] * C + 2 * ln);
        a0.x += v.x; a0.y += v.y;
    }
    a0.x += a1.x + a2.x + a3.x;
    a0.y += a1.y + a2.y + a3.y;

    // cross-warp combine
    sred[wid * C + 2 * ln]     = a0.x;
    sred[wid * C + 2 * ln + 1] = a0.y;
    __syncthreads();

    if (tid < C) {
        float s = 0.f;
#pragma unroll
        for (int w = 0; w < 8; w++) s += sred[w * C + tid];
        float inv = 1.0f / (float)(n > 0 ? n : 1);
        out[(size_t)g * C + tid] = s * inv;
    }
}

extern "C" void kernel_launch(void* const* d_in, const int* in_sizes, int n_in,
                              void* d_out, int out_size) {
    // identify inputs by size (feat = 134217728 elems, map = 2097152 elems)
    const float* feat = nullptr;
    const int*   sp   = nullptr;
    for (int k = 0; k < n_in; k++) {
        if (in_sizes[k] == B * HW * C) feat = (const float*)d_in[k];
        else if (in_sizes[k] == B * HW) sp = (const int*)d_in[k];
    }
    float* out = (float*)d_out;

    k_zero<<<(NSEG * CNT_STRIDE + 255) / 256, 256>>>();
    k_scatter<<<(B * HW) / 1024, 1024>>>(sp);
    k_reduce<<<NSEG, 256>>>(feat, out);
}

// round 12
// speedup vs baseline: 1.0514x; 1.0514x over previous
#include <cuda_runtime.h>
#include <cstdint>

#define S 256            // superpixels per batch
#define B 8
#define HW 262144        // 512*512 pixels per batch
#define C 64
#define NSEG (B * S)     // 2048 global segments
#define CAP 2048         // bucket capacity (expected max ~1140, 2048 is >30 sigma)
#define CNT_STRIDE 32    // 128B padding between counters (spread L2 partitions)

// Scratch (allocation-free __device__ globals; zero-initialized at module load)
__device__ int g_cnt[NSEG * CNT_STRIDE];            // 256 KB
__device__ int g_idx[(size_t)NSEG * CAP];           // 16 MB

// ---------------- Kernel 1: scatter pixel indices into per-segment buckets ----------------
// int4-vectorized label reads; one global atomic per pixel spread over 2048
// 128B-strided counters.
__global__ void k_scatter(const int4* __restrict__ sp) {
    int t = blockIdx.x * blockDim.x + threadIdx.x;   // over B*HW/4, exact grid
    int4 v = sp[t];
    int pixbase = (t << 2) & (HW - 1);
    int b = t >> 16;                                  // (t*4) / HW
    int segs[4] = {v.x, v.y, v.z, v.w};
#pragma unroll
    for (int k = 0; k < 4; k++) {
        int g = b * S + segs[k];
        int pos = atomicAdd(&g_cnt[g * CNT_STRIDE], 1);
        if (pos < CAP) g_idx[(size_t)g * CAP + pos] = pixbase + k;
    }
}

// ---------------- Kernel 2: per-segment gather + mean ----------------
// One CTA per global segment, 256 threads = 8 warps.
// Each warp-load covers 2 pixels (512B): lanes 0-15 -> pixel p (ch 4*(l&15)..+3),
// lanes 16-31 -> pixel p+1. 4-deep unroll = 8 pixels (2KB) in flight per warp.
__global__ void __launch_bounds__(256) k_reduce(const float* __restrict__ feat,
                                                float* __restrict__ out) {
    __shared__ int   sidx[CAP];          // 8 KB
    __shared__ float sred[16 * C];       // 4 KB: 16 partial channel-vectors
    __shared__ int   sn;

    const int g   = blockIdx.x;
    const int b   = g >> 8;
    const int tid = threadIdx.x;
    const int wid = tid >> 5;
    const int ln  = tid & 31;

    // RACE FIX: one thread reads the count AND resets it (sequenced within the
    // thread), publishes via smem; everyone else waits at the barrier. The old
    // code let tid0's reset race against other warps' reads of g_cnt.
    if (tid == 0) {
        sn = g_cnt[g * CNT_STRIDE];
        g_cnt[g * CNT_STRIDE] = 0;       // reset for next graph replay
    }
    __syncthreads();
    int n = sn;
    if (n > CAP) n = CAP;

    // stage indices in smem (coalesced)
    for (int i = tid; i < n; i += 256) sidx[i] = g_idx[(size_t)g * CAP + i];
    __syncthreads();

    const float* fb = feat + (size_t)b * HW * C;
    const int half = ln >> 4;            // which of 2 pixels in the warp-load
    const int cq   = (ln & 15) << 2;     // channel quad owned by this lane

    float4 a0 = make_float4(0.f, 0.f, 0.f, 0.f), a1 = a0, a2 = a0, a3 = a0;

    int i = wid * 2 + half;              // this lane's pixel stream, stride 16
    for (; i + 48 < n; i += 64) {
        float4 v0 = __ldcs((const float4*)(fb + (size_t)sidx[i     ] * C + cq));
        float4 v1 = __ldcs((const float4*)(fb + (size_t)sidx[i + 16] * C + cq));
        float4 v2 = __ldcs((const float4*)(fb + (size_t)sidx[i + 32] * C + cq));
        float4 v3 = __ldcs((const float4*)(fb + (size_t)sidx[i + 48] * C + cq));
        a0.x += v0.x; a0.y += v0.y; a0.z += v0.z; a0.w += v0.w;
        a1.x += v1.x; a1.y += v1.y; a1.z += v1.z; a1.w += v1.w;
        a2.x += v2.x; a2.y += v2.y; a2.z += v2.z; a2.w += v2.w;
        a3.x += v3.x; a3.y += v3.y; a3.z += v3.z; a3.w += v3.w;
    }
    for (; i < n; i += 16) {
        float4 v = __ldcs((const float4*)(fb + (size_t)sidx[i] * C + cq));
        a0.x += v.x; a0.y += v.y; a0.z += v.z; a0.w += v.w;
    }
    a0.x += a1.x + a2.x + a3.x;
    a0.y += a1.y + a2.y + a3.y;
    a0.z += a1.z + a2.z + a3.z;
    a0.w += a1.w + a2.w + a3.w;

    // cross-warp combine: 16 partial sets (8 warps x 2 halves)
    float* dst = &sred[(wid * 2 + half) * C + cq];
    dst[0] = a0.x; dst[1] = a0.y; dst[2] = a0.z; dst[3] = a0.w;
    __syncthreads();

    if (tid < C) {
        float s = 0.f;
#pragma unroll
        for (int k = 0; k < 16; k++) s += sred[k * C + tid];
        float inv = 1.0f / (float)(n > 0 ? n : 1);
        out[(size_t)g * C + tid] = s * inv;
    }
}

extern "C" void kernel_launch(void* const* d_in, const int* in_sizes, int n_in,
                              void* d_out, int out_size) {
    const float* feat = nullptr;
    const int*   sp   = nullptr;
    for (int k = 0; k < n_in; k++) {
        if (in_sizes[k] == B * HW * C) feat = (const float*)d_in[k];
        else if (in_sizes[k] == B * HW) sp = (const int*)d_in[k];
    }
    float* out = (float*)d_out;

    k_scatter<<<(B * HW / 4) / 256, 256>>>((const int4*)sp);
    k_reduce<<<NSEG, 256>>>(feat, out);
}

// round 17
// speedup vs baseline: 1.2774x; 1.2150x over previous
#include <cuda_runtime.h>
#include <cstdint>

#define S 256            // superpixels per batch
#define B 8
#define HW 262144        // 512*512, pixels per batch
#define C 64
#define NSEG (B * S)     // 2048 global segments
#define CAP 2048         // bucket capacity (expected max ~1140, >30 sigma)
#define CNT_STRIDE 32    // 128B padding between counters
#define CHUNK 256        // pixels per reduce work-item
#define NCHUNK (CAP / CHUNK)   // 8 items per segment

// Scratch (allocation-free __device__ globals; zero-initialized at module load,
// and every kernel_launch invocation leaves them zeroed again -> replay-safe)
__device__ int   g_cnt[NSEG * CNT_STRIDE];        // 256 KB
__device__ int   g_idx[(size_t)NSEG * CAP];       // 16 MB
__device__ float g_sum[NSEG * C];                 // 512 KB partial sums

// ---------------- Kernel 1: CTA-aggregated scatter ----------------
// 1024 threads = 4096 pixels per CTA (all same batch: HW/4096 = 64 CTAs/batch).
// smem histogram -> per-(CTA,bin) global reservation -> run-coalesced writes.
__global__ void __launch_bounds__(1024) k_scatter(const int4* __restrict__ sp) {
    __shared__ int hist[S];
    __shared__ int base[S];
    const int tid = threadIdx.x;
    const int t   = blockIdx.x * 1024 + tid;      // int4 id over B*HW/4
    const int b   = blockIdx.x >> 6;              // 64 CTAs per batch

    if (tid < S) hist[tid] = 0;
    __syncthreads();

    int4 v = sp[t];
    int pixbase = (t << 2) & (HW - 1);
    int seg[4] = {v.x, v.y, v.z, v.w};
    int pos[4];
#pragma unroll
    for (int k = 0; k < 4; k++) pos[k] = atomicAdd(&hist[seg[k]], 1);
    __syncthreads();

    if (tid < S) {
        int c = hist[tid];
        base[tid] = (c > 0) ? atomicAdd(&g_cnt[(b * S + tid) * CNT_STRIDE], c) : 0;
    }
    __syncthreads();

#pragma unroll
    for (int k = 0; k < 4; k++) {
        int p = base[seg[k]] + pos[k];
        if (p < CAP)
            g_idx[(size_t)(b * S + seg[k]) * CAP + p] = pixbase + k;
    }
}

// ---------------- Kernel 2: fine-grained gather + partial reduce ----------------
// One CTA per (segment, chunk): grid = NSEG*NCHUNK = 16384 uniform small items.
// 256 threads = 8 warps; warp-load covers 2 pixels (512B, LDG.128 per lane).
__global__ void __launch_bounds__(256) k_reduce(const float* __restrict__ feat) {
    __shared__ int   sidx[CHUNK];        // 1 KB
    __shared__ float sred[16 * C];       // 4 KB

    const int item = blockIdx.x;
    const int g    = item >> 3;          // / NCHUNK
    const int j    = item & (NCHUNK - 1);
    const int tid  = threadIdx.x;
    const int wid  = tid >> 5;
    const int ln   = tid & 31;

    int n = g_cnt[g * CNT_STRIDE];
    if (n > CAP) n = CAP;
    const int lo  = j * CHUNK;
    int cnt = n - lo;
    if (cnt <= 0) return;                // uniform across CTA (no barriers yet)
    if (cnt > CHUNK) cnt = CHUNK;

    if (tid < cnt) sidx[tid] = g_idx[(size_t)g * CAP + lo + tid];
    __syncthreads();

    const int b = g >> 8;
    const float* fb = feat + (size_t)b * HW * C;
    const int half = ln >> 4;            // which of 2 pixels per warp-load
    const int cq   = (ln & 15) << 2;     // channel quad of this lane

    float4 a0 = make_float4(0.f, 0.f, 0.f, 0.f), a1 = a0, a2 = a0, a3 = a0;
    int i = wid * 2 + half;

    if (cnt == CHUNK) {
        // 16 entries per lane-stream (256/16): 4 rounds of 4 independent loads.
#pragma unroll
        for (int r = 0; r < 4; r++) {
            float4 v0 = __ldcs((const float4*)(fb + (size_t)sidx[i     ] * C + cq));
            float4 v1 = __ldcs((const float4*)(fb + (size_t)sidx[i + 16] * C + cq));
            float4 v2 = __ldcs((const float4*)(fb + (size_t)sidx[i + 32] * C + cq));
            float4 v3 = __ldcs((const float4*)(fb + (size_t)sidx[i + 48] * C + cq));
            a0.x += v0.x; a0.y += v0.y; a0.z += v0.z; a0.w += v0.w;
            a1.x += v1.x; a1.y += v1.y; a1.z += v1.z; a1.w += v1.w;
            a2.x += v2.x; a2.y += v2.y; a2.z += v2.z; a2.w += v2.w;
            a3.x += v3.x; a3.y += v3.y; a3.z += v3.z; a3.w += v3.w;
            i += 64;
        }
    } else {
        for (; i < cnt; i += 16) {
            float4 v = __ldcs((const float4*)(fb + (size_t)sidx[i] * C + cq));
            a0.x += v.x; a0.y += v.y; a0.z += v.z; a0.w += v.w;
        }
    }
    a0.x += a1.x + a2.x + a3.x;
    a0.y += a1.y + a2.y + a3.y;
    a0.z += a1.z + a2.z + a3.z;
    a0.w += a1.w + a2.w + a3.w;

    float* dst = &sred[(wid * 2 + half) * C + cq];
    dst[0] = a0.x; dst[1] = a0.y; dst[2] = a0.z; dst[3] = a0.w;
    __syncthreads();

    if (tid < C) {
        float s = 0.f;
#pragma unroll
        for (int k = 0; k < 16; k++) s += sred[k * C + tid];
        atomicAdd(&g_sum[g * C + tid], s);
    }
}

// ---------------- Kernel 3: finalize (divide by count) + scratch reset ----------------
// grid = NSEG*C/256 = 512; 4 segments per CTA (64 threads each).
__global__ void __launch_bounds__(256) k_final(float* __restrict__ out) {
    const int t = blockIdx.x * 256 + threadIdx.x;   // over NSEG*C
    const int g = t >> 6;
    int cnt = g_cnt[g * CNT_STRIDE];
    float s = g_sum[t];
    __syncthreads();                                // reads before resets (CTA-local g)
    if ((t & 63) == 0) g_cnt[g * CNT_STRIDE] = 0;   // replay reset
    g_sum[t] = 0.f;                                 // replay reset
    out[t] = s / (float)(cnt > 0 ? cnt : 1);
}

extern "C" void kernel_launch(void* const* d_in, const int* in_sizes, int n_in,
                              void* d_out, int out_size) {
    const float* feat = nullptr;
    const int*   sp   = nullptr;
    for (int k = 0; k < n_in; k++) {
        if (in_sizes[k] == B * HW * C) feat = (const float*)d_in[k];
        else if (in_sizes[k] == B * HW) sp = (const int*)d_in[k];
    }
    float* out = (float*)d_out;

    k_scatter<<<(B * HW / 4) / 1024, 1024>>>((const int4*)sp);
    k_reduce<<<NSEG * NCHUNK, 256>>>(feat);
    k_final<<<(NSEG * C) / 256, 256>>>(out);
}